// round 1
// baseline (speedup 1.0000x reference)
#include <cuda_runtime.h>

#define NN 50000

// ---------------- scratch (device globals; no allocation allowed) ----------
__device__ float g_xw[(size_t)NN * 512];     // GEMM output scratch
__device__ float g_agg[(size_t)NN * 512];    // aggregation scratch
__device__ float g_h1[(size_t)NN * 256];
__device__ float g_h2[(size_t)NN * 512];
__device__ float g_h4in[(size_t)NN * 256];
__device__ float g_h4[(size_t)NN * 128];
__device__ float g_dinv[NN];
__device__ float g_deg[NN];
__device__ int   g_is64;

// ---------------- helpers ---------------------------------------------------
__device__ __forceinline__ void red_add_v4(float* p, float4 v) {
    asm volatile("red.global.add.v4.f32 [%0], {%1,%2,%3,%4};"
                 :: "l"(p), "f"(v.x), "f"(v.y), "f"(v.z), "f"(v.w)
                 : "memory");
}

// Detect whether edge_index is int64 (high 32-bit words of first 512 entries all 0)
__global__ void detect_k(const unsigned int* __restrict__ e) {
    __shared__ int ok;
    if (threadIdx.x == 0) ok = 1;
    __syncthreads();
    for (int i = threadIdx.x; i < 512; i += blockDim.x)
        if (e[2 * i + 1] != 0u) ok = 0;
    __syncthreads();
    if (threadIdx.x == 0) g_is64 = ok;
}

__global__ void deg_init_k() {
    int i = blockIdx.x * blockDim.x + threadIdx.x;
    if (i < NN) g_deg[i] = 1.0f;   // self loop
}

__global__ void deg_count_k(const unsigned int* __restrict__ e, long long E) {
    long long i = (long long)blockIdx.x * blockDim.x + threadIdx.x;
    if (i >= E) return;
    int is64 = g_is64;
    int d = is64 ? (int)e[2 * (E + i)] : (int)e[E + i];
    atomicAdd(&g_deg[d], 1.0f);
}

__global__ void dinv_k() {
    int i = blockIdx.x * blockDim.x + threadIdx.x;
    if (i < NN) g_dinv[i] = rsqrtf(g_deg[i]);
}

// ---------------- SGEMM: C[M,Nn] = A[M,K] @ B[K,Nn] (row-major) -------------
// 128x128 tile, BK=8, 256 threads, 8x8 per thread. Nn % 128 == 0, K % 8 == 0.
__global__ __launch_bounds__(256) void sgemm_k(
    const float* __restrict__ A, const float* __restrict__ B,
    float* __restrict__ C, int M, int Nn, int K)
{
    __shared__ float As[8][128];
    __shared__ float Bs[8][128];
    int tid = threadIdx.x;
    int tx = tid & 15, ty = tid >> 4;
    int rowBase = blockIdx.y * 128;
    int colBase = blockIdx.x * 128;

    int aRow  = tid >> 1;          // 0..127
    int aCol4 = (tid & 1) * 4;     // 0 or 4
    int bRow  = tid >> 5;          // 0..7
    int bCol  = (tid & 31) * 4;    // 0..124

    float acc[8][8];
#pragma unroll
    for (int i = 0; i < 8; i++)
#pragma unroll
        for (int j = 0; j < 8; j++) acc[i][j] = 0.0f;

    for (int k0 = 0; k0 < K; k0 += 8) {
        float4 av = make_float4(0.f, 0.f, 0.f, 0.f);
        int gr = rowBase + aRow;
        if (gr < M) av = *(const float4*)&A[(size_t)gr * K + k0 + aCol4];
        As[aCol4 + 0][aRow] = av.x;
        As[aCol4 + 1][aRow] = av.y;
        As[aCol4 + 2][aRow] = av.z;
        As[aCol4 + 3][aRow] = av.w;
        *(float4*)&Bs[bRow][bCol] =
            *(const float4*)&B[(size_t)(k0 + bRow) * Nn + colBase + bCol];
        __syncthreads();
#pragma unroll
        for (int k = 0; k < 8; k++) {
            float a[8], b[8];
            *(float4*)&a[0] = *(const float4*)&As[k][ty * 8];
            *(float4*)&a[4] = *(const float4*)&As[k][ty * 8 + 4];
            *(float4*)&b[0] = *(const float4*)&Bs[k][tx * 8];
            *(float4*)&b[4] = *(const float4*)&Bs[k][tx * 8 + 4];
#pragma unroll
            for (int i = 0; i < 8; i++)
#pragma unroll
                for (int j = 0; j < 8; j++) acc[i][j] += a[i] * b[j];
        }
        __syncthreads();
    }
#pragma unroll
    for (int i = 0; i < 8; i++) {
        int r = rowBase + ty * 8 + i;
        if (r < M) {
            float* cp = &C[(size_t)r * Nn + colBase + tx * 8];
            *(float4*)&cp[0] = make_float4(acc[i][0], acc[i][1], acc[i][2], acc[i][3]);
            *(float4*)&cp[4] = make_float4(acc[i][4], acc[i][5], acc[i][6], acc[i][7]);
        }
    }
}

// ---------------- AGG init: self-loop message + bias (no atomics) ----------
__global__ void selfloop_bias_k(const float* __restrict__ xw,
                                const float* __restrict__ b,
                                float* __restrict__ agg, int F) {
    int idx = blockIdx.x * blockDim.x + threadIdx.x;   // float4 index
    int f4pr = F >> 2;
    int total = NN * f4pr;
    if (idx >= total) return;
    int node = idx / f4pr;
    int f4 = idx - node * f4pr;
    float s = g_dinv[node]; s *= s;
    float4 v = ((const float4*)xw)[idx];
    float4 bb = ((const float4*)b)[f4];
    float4 o = make_float4(v.x * s + bb.x, v.y * s + bb.y,
                           v.z * s + bb.z, v.w * s + bb.w);
    ((float4*)agg)[idx] = o;
}

// ---------------- edge scatter: warp per edge, vector red ------------------
__global__ void scatter_k(const unsigned int* __restrict__ e, long long E,
                          const float* __restrict__ xw,
                          float* __restrict__ agg, int F) {
    long long gw = ((long long)blockIdx.x * blockDim.x + threadIdx.x) >> 5;
    int lane = threadIdx.x & 31;
    if (gw >= E) return;
    int is64 = g_is64;
    int s, d;
    if (is64) { s = (int)e[2 * gw];  d = (int)e[2 * (E + gw)]; }
    else      { s = (int)e[gw];      d = (int)e[E + gw]; }
    float nrm = g_dinv[s] * g_dinv[d];
    const float4* sp = (const float4*)(xw + (size_t)s * F);
    float* dp = agg + (size_t)d * F;
    int F4 = F >> 2;
    for (int f = lane; f < F4; f += 32) {
        float4 v = sp[f];
        v.x *= nrm; v.y *= nrm; v.z *= nrm; v.w *= nrm;
        red_add_v4(dp + (f << 2), v);
    }
}

// ---------------- fused LayerNorm + ELU (+residual, +tap outputs) ----------
// blockDim = F/4 threads (32/64/128), one block per node.
__global__ void ln_elu_k(const float* __restrict__ in,
                         const float* __restrict__ gamma,
                         const float* __restrict__ beta,
                         float* __restrict__ out, int F,
                         const float* __restrict__ resid,
                         float* __restrict__ out_raw,
                         float* __restrict__ out_bn) {
    int node = blockIdx.x;
    int tid = threadIdx.x;
    int nw = blockDim.x >> 5;
    const float4* row = (const float4*)(in + (size_t)node * F);
    float4 v = row[tid];
    float s = v.x + v.y + v.z + v.w;
    float q = v.x * v.x + v.y * v.y + v.z * v.z + v.w * v.w;
#pragma unroll
    for (int o = 16; o > 0; o >>= 1) {
        s += __shfl_xor_sync(0xffffffffu, s, o);
        q += __shfl_xor_sync(0xffffffffu, q, o);
    }
    __shared__ float ss[4], sq[4];
    int wid = tid >> 5, lane = tid & 31;
    if (nw > 1) {
        if (lane == 0) { ss[wid] = s; sq[wid] = q; }
        __syncthreads();
        s = 0.f; q = 0.f;
        for (int w = 0; w < nw; w++) { s += ss[w]; q += sq[w]; }
    }
    float invF = 1.0f / F;
    float mu = s * invF;
    float var = q * invF - mu * mu;
    float rstd = rsqrtf(var + 1e-5f);
    float4 gv = ((const float4*)gamma)[tid];
    float4 bv = ((const float4*)beta)[tid];
    float4 y;
    y.x = (v.x - mu) * rstd * gv.x + bv.x;
    y.y = (v.y - mu) * rstd * gv.y + bv.y;
    y.z = (v.z - mu) * rstd * gv.z + bv.z;
    y.w = (v.w - mu) * rstd * gv.w + bv.w;
    float4 eo;
    eo.x = y.x > 0.f ? y.x : expm1f(y.x);
    eo.y = y.y > 0.f ? y.y : expm1f(y.y);
    eo.z = y.z > 0.f ? y.z : expm1f(y.z);
    eo.w = y.w > 0.f ? y.w : expm1f(y.w);
    if (out_raw) ((float4*)(out_raw + (size_t)node * F))[tid] = v;
    if (out_bn)  ((float4*)(out_bn  + (size_t)node * F))[tid] = y;
    if (resid) {
        float4 r = ((const float4*)(resid + (size_t)node * F))[tid];
        eo.x += r.x; eo.y += r.y; eo.z += r.z; eo.w += r.w;
    }
    ((float4*)(out + (size_t)node * F))[tid] = eo;
}

// ---------------- classifier: [N,128] @ [128,4] + bc -----------------------
__global__ void classifier_k(const float* __restrict__ h,
                             const float* __restrict__ Wc,
                             const float* __restrict__ bc,
                             float* __restrict__ out) {
    int warp = (blockIdx.x * blockDim.x + threadIdx.x) >> 5;
    int lane = threadIdx.x & 31;
    if (warp >= NN) return;
    const float* row = h + (size_t)warp * 128;
    float a0 = 0.f, a1 = 0.f, a2 = 0.f, a3 = 0.f;
    for (int k = lane; k < 128; k += 32) {
        float v = row[k];
        a0 += v * Wc[k * 4 + 0];
        a1 += v * Wc[k * 4 + 1];
        a2 += v * Wc[k * 4 + 2];
        a3 += v * Wc[k * 4 + 3];
    }
#pragma unroll
    for (int o = 16; o > 0; o >>= 1) {
        a0 += __shfl_down_sync(0xffffffffu, a0, o);
        a1 += __shfl_down_sync(0xffffffffu, a1, o);
        a2 += __shfl_down_sync(0xffffffffu, a2, o);
        a3 += __shfl_down_sync(0xffffffffu, a3, o);
    }
    if (lane == 0) {
        out[(size_t)warp * 4 + 0] = a0 + bc[0];
        out[(size_t)warp * 4 + 1] = a1 + bc[1];
        out[(size_t)warp * 4 + 2] = a2 + bc[2];
        out[(size_t)warp * 4 + 3] = a3 + bc[3];
    }
}

// ---------------- host launch ----------------------------------------------
static inline void* sym(const void* s) {
    void* p = nullptr;
    cudaGetSymbolAddress(&p, s);
    return p;
}

extern "C" void kernel_launch(void* const* d_in, const int* in_sizes, int n_in,
                              void* d_out, int out_size) {
    const float* x  = (const float*)d_in[0];
    const unsigned int* e = (const unsigned int*)d_in[1];
    const float* W1 = (const float*)d_in[2];  const float* b1 = (const float*)d_in[3];
    const float* W2 = (const float*)d_in[4];  const float* b2 = (const float*)d_in[5];
    const float* W3 = (const float*)d_in[6];  const float* b3 = (const float*)d_in[7];
    const float* W4 = (const float*)d_in[8];  const float* b4 = (const float*)d_in[9];
    const float* Wc = (const float*)d_in[10]; const float* bc = (const float*)d_in[11];
    const float* g1 = (const float*)d_in[12]; const float* be1 = (const float*)d_in[13];
    const float* g2 = (const float*)d_in[14]; const float* be2 = (const float*)d_in[15];
    const float* g3 = (const float*)d_in[16]; const float* be3 = (const float*)d_in[17];
    const float* g4 = (const float*)d_in[18]; const float* be4 = (const float*)d_in[19];

    long long E = (long long)in_sizes[1] / 2;

    float* out        = (float*)d_out;
    float* out_logits = out;
    float* out_conv   = out + (size_t)NN * 4;
    float* out_bn     = out_conv + (size_t)NN * 128;

    float* xw   = (float*)sym(g_xw);
    float* agg  = (float*)sym(g_agg);
    float* h1   = (float*)sym(g_h1);
    float* h2   = (float*)sym(g_h2);
    float* h4in = (float*)sym(g_h4in);
    float* h4   = (float*)sym(g_h4);

    // ---- edge prep ----
    detect_k<<<1, 256>>>(e);
    deg_init_k<<<(NN + 255) / 256, 256>>>();
    deg_count_k<<<(unsigned)((E + 255) / 256), 256>>>(e, E);
    dinv_k<<<(NN + 255) / 256, 256>>>();

    unsigned scat_blocks = (unsigned)((E * 32 + 255) / 256);
    int mgrid = (NN + 127) / 128;

    // ---- layer 1: x[.,512] @ W1[512,256] ----
    sgemm_k<<<dim3(256 / 128, mgrid), 256>>>(x, W1, xw, NN, 256, 512);
    selfloop_bias_k<<<(NN * 64 + 255) / 256, 256>>>(xw, b1, agg, 256);
    scatter_k<<<scat_blocks, 256>>>(e, E, xw, agg, 256);
    ln_elu_k<<<NN, 64>>>(agg, g1, be1, h1, 256, nullptr, nullptr, nullptr);

    // ---- layer 2: h1[.,256] @ W2[256,512] ----
    sgemm_k<<<dim3(512 / 128, mgrid), 256>>>(h1, W2, xw, NN, 512, 256);
    selfloop_bias_k<<<(NN * 128 + 255) / 256, 256>>>(xw, b2, agg, 512);
    scatter_k<<<scat_blocks, 256>>>(e, E, xw, agg, 512);
    ln_elu_k<<<NN, 128>>>(agg, g2, be2, h2, 512, nullptr, nullptr, nullptr);

    // ---- layer 3: h2[.,512] @ W3[512,256]; fused residual h3 + h1 ----
    sgemm_k<<<dim3(256 / 128, mgrid), 256>>>(h2, W3, xw, NN, 256, 512);
    selfloop_bias_k<<<(NN * 64 + 255) / 256, 256>>>(xw, b3, agg, 256);
    scatter_k<<<scat_blocks, 256>>>(e, E, xw, agg, 256);
    ln_elu_k<<<NN, 64>>>(agg, g3, be3, h4in, 256, h1, nullptr, nullptr);

    // ---- layer 4: h4in[.,256] @ W4[256,128]; taps out_conv/out_bn ----
    sgemm_k<<<dim3(128 / 128, mgrid), 256>>>(h4in, W4, xw, NN, 128, 256);
    selfloop_bias_k<<<(NN * 32 + 255) / 256, 256>>>(xw, b4, agg, 128);
    scatter_k<<<scat_blocks, 256>>>(e, E, xw, agg, 128);
    ln_elu_k<<<NN, 32>>>(agg, g4, be4, h4, 128, nullptr, out_conv, out_bn);

    // ---- classifier ----
    classifier_k<<<(NN * 32 + 127) / 128, 128>>>(h4, Wc, bc, out_logits);
}

// round 2
// speedup vs baseline: 1.8214x; 1.8214x over previous
#include <cuda_runtime.h>

#define NN 50000
#define EMAX 1700000
#define SCAN_B 512
#define NB ((NN + SCAN_B - 1) / SCAN_B)   // 98

// ---------------- scratch (device globals; no allocation allowed) ----------
__device__ float g_xw[(size_t)NN * 512];     // GEMM output scratch
__device__ float g_h1[(size_t)NN * 256];
__device__ float g_h2[(size_t)NN * 512];
__device__ float g_h4in[(size_t)NN * 256];
__device__ float g_h4[(size_t)NN * 128];
__device__ float g_dinv[NN];
__device__ int   g_degi[NN];
__device__ int   g_off[NN];
__device__ int   g_cur[NN];
__device__ int   g_bsum[NB];
__device__ int   g_btop[NB];
__device__ int   g_csr[EMAX];
__device__ float g_nrm[EMAX];
__device__ int   g_is64;

// ---------------- edge-format detect ---------------------------------------
__global__ void detect_k(const unsigned int* __restrict__ e) {
    __shared__ int ok;
    if (threadIdx.x == 0) ok = 1;
    __syncthreads();
    for (int i = threadIdx.x; i < 512; i += blockDim.x)
        if (e[2 * i + 1] != 0u) ok = 0;
    __syncthreads();
    if (threadIdx.x == 0) g_is64 = ok;
}

__device__ __forceinline__ void edge_sd(const unsigned int* e, long long E,
                                        long long i, int& s, int& d) {
    if (g_is64) { s = (int)e[2 * i]; d = (int)e[2 * (E + i)]; }
    else        { s = (int)e[i];     d = (int)e[E + i]; }
}

// ---------------- CSR build -------------------------------------------------
__global__ void zero_deg_k() {
    int i = blockIdx.x * blockDim.x + threadIdx.x;
    if (i < NN) g_degi[i] = 0;
}

__global__ void hist_k(const unsigned int* __restrict__ e, long long E) {
    long long i = (long long)blockIdx.x * blockDim.x + threadIdx.x;
    if (i >= E) return;
    int d = g_is64 ? (int)e[2 * (E + i)] : (int)e[E + i];
    atomicAdd(&g_degi[d], 1);
}

__global__ void dinv_k() {
    int i = blockIdx.x * blockDim.x + threadIdx.x;
    if (i < NN) g_dinv[i] = rsqrtf((float)g_degi[i] + 1.0f);  // +1 self loop
}

__global__ void scan1_k() {
    __shared__ int sh[SCAN_B];
    int i = blockIdx.x * SCAN_B + threadIdx.x;
    int v = (i < NN) ? g_degi[i] : 0;
    sh[threadIdx.x] = v;
    __syncthreads();
#pragma unroll
    for (int o = 1; o < SCAN_B; o <<= 1) {
        int t = (threadIdx.x >= o) ? sh[threadIdx.x - o] : 0;
        __syncthreads();
        sh[threadIdx.x] += t;
        __syncthreads();
    }
    if (i < NN) g_off[i] = sh[threadIdx.x] - v;   // exclusive within block
    if (threadIdx.x == SCAN_B - 1) g_bsum[blockIdx.x] = sh[SCAN_B - 1];
}

__global__ void scan2_k() {
    if (threadIdx.x == 0) {
        int acc = 0;
        for (int b = 0; b < NB; b++) { int t = g_bsum[b]; g_btop[b] = acc; acc += t; }
    }
}

__global__ void scan3_k() {
    int i = blockIdx.x * blockDim.x + threadIdx.x;
    if (i < NN) {
        int o = g_off[i] + g_btop[i / SCAN_B];
        g_off[i] = o;
        g_cur[i] = o;
    }
}

__global__ void fill_k(const unsigned int* __restrict__ e, long long E) {
    long long i = (long long)blockIdx.x * blockDim.x + threadIdx.x;
    if (i >= E) return;
    int s, d;
    edge_sd(e, E, i, s, d);
    int pos = atomicAdd(&g_cur[d], 1);
    g_csr[pos] = s;
    g_nrm[pos] = g_dinv[s] * g_dinv[d];
}

// ---------------- SGEMM: C[M,Nn] = A[M,K] @ B[K,Nn] (row-major) -------------
__global__ __launch_bounds__(256) void sgemm_k(
    const float* __restrict__ A, const float* __restrict__ B,
    float* __restrict__ C, int M, int Nn, int K)
{
    __shared__ float As[8][128];
    __shared__ float Bs[8][128];
    int tid = threadIdx.x;
    int tx = tid & 15, ty = tid >> 4;
    int rowBase = blockIdx.y * 128;
    int colBase = blockIdx.x * 128;

    int aRow  = tid >> 1;
    int aCol4 = (tid & 1) * 4;
    int bRow  = tid >> 5;
    int bCol  = (tid & 31) * 4;

    float acc[8][8];
#pragma unroll
    for (int i = 0; i < 8; i++)
#pragma unroll
        for (int j = 0; j < 8; j++) acc[i][j] = 0.0f;

    for (int k0 = 0; k0 < K; k0 += 8) {
        float4 av = make_float4(0.f, 0.f, 0.f, 0.f);
        int gr = rowBase + aRow;
        if (gr < M) av = *(const float4*)&A[(size_t)gr * K + k0 + aCol4];
        As[aCol4 + 0][aRow] = av.x;
        As[aCol4 + 1][aRow] = av.y;
        As[aCol4 + 2][aRow] = av.z;
        As[aCol4 + 3][aRow] = av.w;
        *(float4*)&Bs[bRow][bCol] =
            *(const float4*)&B[(size_t)(k0 + bRow) * Nn + colBase + bCol];
        __syncthreads();
#pragma unroll
        for (int k = 0; k < 8; k++) {
            float a[8], b[8];
            *(float4*)&a[0] = *(const float4*)&As[k][ty * 8];
            *(float4*)&a[4] = *(const float4*)&As[k][ty * 8 + 4];
            *(float4*)&b[0] = *(const float4*)&Bs[k][tx * 8];
            *(float4*)&b[4] = *(const float4*)&Bs[k][tx * 8 + 4];
#pragma unroll
            for (int i = 0; i < 8; i++)
#pragma unroll
                for (int j = 0; j < 8; j++) acc[i][j] += a[i] * b[j];
        }
        __syncthreads();
    }
#pragma unroll
    for (int i = 0; i < 8; i++) {
        int r = rowBase + ty * 8 + i;
        if (r < M) {
            float* cp = &C[(size_t)r * Nn + colBase + tx * 8];
            *(float4*)&cp[0] = make_float4(acc[i][0], acc[i][1], acc[i][2], acc[i][3]);
            *(float4*)&cp[4] = make_float4(acc[i][4], acc[i][5], acc[i][6], acc[i][7]);
        }
    }
}

// ---------------- fused warp-per-node: CSR gather + self + bias + LN + ELU --
// One warp owns one dst node; accumulators live in registers (float4).
template<int F>
__global__ __launch_bounds__(256) void agg_ln_elu_k(
    const float* __restrict__ xw,
    const float* __restrict__ bias,
    const float* __restrict__ gamma,
    const float* __restrict__ beta,
    float* __restrict__ out,
    const float* __restrict__ resid,
    float* __restrict__ out_raw,
    float* __restrict__ out_bn)
{
    constexpr int RF = F / 128;   // float4 accumulators per lane
    int warp = (blockIdx.x * blockDim.x + threadIdx.x) >> 5;
    int lane = threadIdx.x & 31;
    if (warp >= NN) return;
    int d = warp;

    float4 acc[RF];
#pragma unroll
    for (int i = 0; i < RF; i++) acc[i] = make_float4(0.f, 0.f, 0.f, 0.f);

    int beg = g_off[d];
    int cnt = g_degi[d];

    for (int b0 = 0; b0 < cnt; b0 += 32) {
        int n = min(32, cnt - b0);
        int   s_l = 0;
        float n_l = 0.f;
        if (lane < n) {
            s_l = g_csr[beg + b0 + lane];
            n_l = g_nrm[beg + b0 + lane];
        }
        for (int j = 0; j < n; j++) {
            int   s   = __shfl_sync(0xffffffffu, s_l, j);
            float nrm = __shfl_sync(0xffffffffu, n_l, j);
            const float4* row = (const float4*)(xw + (size_t)s * F);
#pragma unroll
            for (int i = 0; i < RF; i++) {
                float4 v = row[i * 32 + lane];
                acc[i].x = fmaf(nrm, v.x, acc[i].x);
                acc[i].y = fmaf(nrm, v.y, acc[i].y);
                acc[i].z = fmaf(nrm, v.z, acc[i].z);
                acc[i].w = fmaf(nrm, v.w, acc[i].w);
            }
        }
    }

    // self-loop + bias
    {
        float dd = g_dinv[d];
        float nrm = dd * dd;
        const float4* row = (const float4*)(xw + (size_t)d * F);
        const float4* bb  = (const float4*)bias;
#pragma unroll
        for (int i = 0; i < RF; i++) {
            float4 v = row[i * 32 + lane];
            float4 b = bb[i * 32 + lane];
            acc[i].x = fmaf(nrm, v.x, acc[i].x) + b.x;
            acc[i].y = fmaf(nrm, v.y, acc[i].y) + b.y;
            acc[i].z = fmaf(nrm, v.z, acc[i].z) + b.z;
            acc[i].w = fmaf(nrm, v.w, acc[i].w) + b.w;
        }
    }

    // LayerNorm stats (warp-wide over F features)
    float s = 0.f, q = 0.f;
#pragma unroll
    for (int i = 0; i < RF; i++) {
        s += acc[i].x + acc[i].y + acc[i].z + acc[i].w;
        q += acc[i].x * acc[i].x + acc[i].y * acc[i].y
           + acc[i].z * acc[i].z + acc[i].w * acc[i].w;
    }
#pragma unroll
    for (int o = 16; o > 0; o >>= 1) {
        s += __shfl_xor_sync(0xffffffffu, s, o);
        q += __shfl_xor_sync(0xffffffffu, q, o);
    }
    constexpr float invF = 1.0f / F;
    float mu = s * invF;
    float var = q * invF - mu * mu;
    float rstd = rsqrtf(var + 1e-5f);

    const float4* gp = (const float4*)gamma;
    const float4* bp = (const float4*)beta;
    float4* op = (float4*)(out + (size_t)d * F);
    const float4* rp = resid ? (const float4*)(resid + (size_t)d * F) : nullptr;
    float4* rawp = out_raw ? (float4*)(out_raw + (size_t)d * F) : nullptr;
    float4* bnp  = out_bn  ? (float4*)(out_bn  + (size_t)d * F) : nullptr;

#pragma unroll
    for (int i = 0; i < RF; i++) {
        int idx = i * 32 + lane;
        float4 gv = gp[idx];
        float4 bv = bp[idx];
        float4 y;
        y.x = (acc[i].x - mu) * rstd * gv.x + bv.x;
        y.y = (acc[i].y - mu) * rstd * gv.y + bv.y;
        y.z = (acc[i].z - mu) * rstd * gv.z + bv.z;
        y.w = (acc[i].w - mu) * rstd * gv.w + bv.w;
        if (rawp) rawp[idx] = acc[i];
        if (bnp)  bnp[idx]  = y;
        float4 eo;
        eo.x = y.x > 0.f ? y.x : expm1f(y.x);
        eo.y = y.y > 0.f ? y.y : expm1f(y.y);
        eo.z = y.z > 0.f ? y.z : expm1f(y.z);
        eo.w = y.w > 0.f ? y.w : expm1f(y.w);
        if (rp) {
            float4 r = rp[idx];
            eo.x += r.x; eo.y += r.y; eo.z += r.z; eo.w += r.w;
        }
        op[idx] = eo;
    }
}

// ---------------- classifier: [N,128] @ [128,4] + bc -----------------------
__global__ void classifier_k(const float* __restrict__ h,
                             const float* __restrict__ Wc,
                             const float* __restrict__ bc,
                             float* __restrict__ out) {
    int warp = (blockIdx.x * blockDim.x + threadIdx.x) >> 5;
    int lane = threadIdx.x & 31;
    if (warp >= NN) return;
    const float* row = h + (size_t)warp * 128;
    float a0 = 0.f, a1 = 0.f, a2 = 0.f, a3 = 0.f;
    for (int k = lane; k < 128; k += 32) {
        float v = row[k];
        a0 += v * Wc[k * 4 + 0];
        a1 += v * Wc[k * 4 + 1];
        a2 += v * Wc[k * 4 + 2];
        a3 += v * Wc[k * 4 + 3];
    }
#pragma unroll
    for (int o = 16; o > 0; o >>= 1) {
        a0 += __shfl_down_sync(0xffffffffu, a0, o);
        a1 += __shfl_down_sync(0xffffffffu, a1, o);
        a2 += __shfl_down_sync(0xffffffffu, a2, o);
        a3 += __shfl_down_sync(0xffffffffu, a3, o);
    }
    if (lane == 0) {
        out[(size_t)warp * 4 + 0] = a0 + bc[0];
        out[(size_t)warp * 4 + 1] = a1 + bc[1];
        out[(size_t)warp * 4 + 2] = a2 + bc[2];
        out[(size_t)warp * 4 + 3] = a3 + bc[3];
    }
}

// ---------------- host launch ----------------------------------------------
static inline void* sym(const void* s) {
    void* p = nullptr;
    cudaGetSymbolAddress(&p, s);
    return p;
}

extern "C" void kernel_launch(void* const* d_in, const int* in_sizes, int n_in,
                              void* d_out, int out_size) {
    const float* x  = (const float*)d_in[0];
    const unsigned int* e = (const unsigned int*)d_in[1];
    const float* W1 = (const float*)d_in[2];  const float* b1 = (const float*)d_in[3];
    const float* W2 = (const float*)d_in[4];  const float* b2 = (const float*)d_in[5];
    const float* W3 = (const float*)d_in[6];  const float* b3 = (const float*)d_in[7];
    const float* W4 = (const float*)d_in[8];  const float* b4 = (const float*)d_in[9];
    const float* Wc = (const float*)d_in[10]; const float* bc = (const float*)d_in[11];
    const float* g1 = (const float*)d_in[12]; const float* be1 = (const float*)d_in[13];
    const float* g2 = (const float*)d_in[14]; const float* be2 = (const float*)d_in[15];
    const float* g3 = (const float*)d_in[16]; const float* be3 = (const float*)d_in[17];
    const float* g4 = (const float*)d_in[18]; const float* be4 = (const float*)d_in[19];

    long long E = (long long)in_sizes[1] / 2;

    float* out        = (float*)d_out;
    float* out_logits = out;
    float* out_conv   = out + (size_t)NN * 4;
    float* out_bn     = out_conv + (size_t)NN * 128;

    float* xw   = (float*)sym(g_xw);
    float* h1   = (float*)sym(g_h1);
    float* h2   = (float*)sym(g_h2);
    float* h4in = (float*)sym(g_h4in);
    float* h4   = (float*)sym(g_h4);

    // ---- CSR build (per replay) ----
    detect_k<<<1, 256>>>(e);
    zero_deg_k<<<(NN + 255) / 256, 256>>>();
    hist_k<<<(unsigned)((E + 255) / 256), 256>>>(e, E);
    dinv_k<<<(NN + 255) / 256, 256>>>();
    scan1_k<<<NB, SCAN_B>>>();
    scan2_k<<<1, 32>>>();
    scan3_k<<<(NN + 255) / 256, 256>>>();
    fill_k<<<(unsigned)((E + 255) / 256), 256>>>(e, E);

    int mgrid = (NN + 127) / 128;
    unsigned agg_blocks = (NN * 32 + 255) / 256;   // warp per node, 256-thread blocks

    // ---- layer 1: x[.,512] @ W1[512,256] ----
    sgemm_k<<<dim3(2, mgrid), 256>>>(x, W1, xw, NN, 256, 512);
    agg_ln_elu_k<256><<<agg_blocks, 256>>>(xw, b1, g1, be1, h1, nullptr, nullptr, nullptr);

    // ---- layer 2: h1[.,256] @ W2[256,512] ----
    sgemm_k<<<dim3(4, mgrid), 256>>>(h1, W2, xw, NN, 512, 256);
    agg_ln_elu_k<512><<<agg_blocks, 256>>>(xw, b2, g2, be2, h2, nullptr, nullptr, nullptr);

    // ---- layer 3: h2[.,512] @ W3[512,256]; fused residual + h1 ----
    sgemm_k<<<dim3(2, mgrid), 256>>>(h2, W3, xw, NN, 256, 512);
    agg_ln_elu_k<256><<<agg_blocks, 256>>>(xw, b3, g3, be3, h4in, h1, nullptr, nullptr);

    // ---- layer 4: h4in[.,256] @ W4[256,128]; taps out_conv/out_bn ----
    sgemm_k<<<dim3(1, mgrid), 256>>>(h4in, W4, xw, NN, 128, 256);
    agg_ln_elu_k<128><<<agg_blocks, 256>>>(xw, b4, g4, be4, h4, nullptr, out_conv, out_bn);

    // ---- classifier ----
    classifier_k<<<(NN * 32 + 127) / 128, 128>>>(h4, Wc, bc, out_logits);
}